// round 15
// baseline (speedup 1.0000x reference)
#include <cuda_runtime.h>
#include <math.h>

// Problem constants
#define BB 256   // batch
#define TT 512   // time steps
#define DD 64    // input dim (layer 0)
#define HH 256   // hidden dim
#define G4H 1024 // 4*H

#define NBLK 128     // persistent grid size (16 CTA-octets), 1 block/SM
#define RTHREADS 256 // 8 warps = 2 gatecol-halves x 4 K-quarters
#define GRPSZ 8      // CTAs per sync group
#define BM 8         // batch rows per group (2 groups per CTA)

typedef unsigned long long ull;

// ---------------- scratch (__device__ globals; no allocations allowed) ----------
__device__ float    g_xproj[(size_t)TT * BB * G4H]; // 512 MB: x @ W_ih^T + bias, [T][B][4H]
__device__ float    g_h0T[(size_t)TT * HH * BB];    // 128 MB: layer-0 outputs TRANSPOSED [T][H][B]
__device__ float    g_hT[2][HH * BB];               // ping-pong h state, TRANSPOSED [H][B]
__device__ unsigned g_ctr[2][32 * 64];              // per-group counters, 256B apart

// ---------------- packed fp32x2 helpers (Blackwell FFMA2 via PTX) ---------------
__device__ __forceinline__ ull pack2(float lo, float hi) {
    ull r;
    asm("mov.b64 %0, {%1, %2};" : "=l"(r) : "f"(lo), "f"(hi));
    return r;
}
__device__ __forceinline__ void unpack2(ull v, float& lo, float& hi) {
    asm("mov.b64 {%0, %1}, %2;" : "=f"(lo), "=f"(hi) : "l"(v));
}
__device__ __forceinline__ void fma2(ull& d, ull a, ull b) {
    asm("fma.rn.f32x2 %0, %1, %2, %0;" : "+l"(d) : "l"(a), "l"(b));
}

// ---------------- fast activations (MUFU-based, ~1e-6 rel err) ------------------
__device__ __forceinline__ float sigf(float x) {
    return __fdividef(1.0f, 1.0f + __expf(-x));
}
__device__ __forceinline__ float tanf_fast(float x) {
    return __fdividef(2.0f, 1.0f + __expf(-2.0f * x)) - 1.0f;
}

// ---------------- group barrier primitives ---------------------------------------
__device__ __forceinline__ void bar_red(unsigned* ctr) {
    asm volatile("red.release.gpu.add.u32 [%0], 1;" :: "l"(ctr) : "memory");
}
__device__ __forceinline__ unsigned ld_acq(const unsigned* p) {
    unsigned v;
    asm volatile("ld.acquire.gpu.u32 %0, [%1];" : "=r"(v) : "l"(p) : "memory");
    return v;
}

// ================================================================================
// Input-projection GEMM (best-measured version, unchanged):
// out[m][gc] = sum_k A[m][k] * W[gc][k] + b_ih[gc] + b_hh[gc], m = t*BB + b.
// AMODE 0: A = x [B][T][D].  AMODE 1: A = g_h0T [T][H][B] (transposed).
// ================================================================================
template<int K, int AMODE>
__global__ __launch_bounds__(256)
void xproj_gemm(const float* __restrict__ A,
                const float* __restrict__ W,
                const float* __restrict__ bih,
                const float* __restrict__ bhh,
                float* __restrict__ out)
{
    __shared__ float At[32 * 68];    // [k][row], padded
    __shared__ float Wt[32 * 130];   // [k][col], even pad (8B-aligned rows)

    const int tid = threadIdx.x;
    const int tx  = tid & 15;        // col-pair lane: cols 2tx + 32j
    const int ty  = tid >> 4;        // rows ty + 16r
    const int m0  = blockIdx.x * 64;
    const int n0  = blockIdx.y * 128;

    ull acc[4][4];
#pragma unroll
    for (int r = 0; r < 4; r++)
#pragma unroll
        for (int j = 0; j < 4; j++) acc[r][j] = 0ull;

    for (int ks = 0; ks < K; ks += 32) {
        if (AMODE == 0) {
#pragma unroll
            for (int q = 0; q < 2; q++) {
                int chunk = tid + 256 * q;          // 512 float4 chunks
                int row   = chunk >> 3;
                int kq    = (chunk & 7) << 2;
                int m     = m0 + row;
                const float* ap = A + (size_t)(m & 255) * (TT * DD)
                                    + (size_t)(m >> 8) * DD + ks + kq;
                float4 v = *reinterpret_cast<const float4*>(ap);
                At[(kq + 0) * 68 + row] = v.x;
                At[(kq + 1) * 68 + row] = v.y;
                At[(kq + 2) * 68 + row] = v.z;
                At[(kq + 3) * 68 + row] = v.w;
            }
        } else {
            int t  = m0 >> 8;
            int b0 = m0 & 255;
#pragma unroll
            for (int q = 0; q < 2; q++) {
                int chunk = tid + 256 * q;          // 512 float4 chunks
                int k  = chunk >> 4;                // 0..31
                int b4 = (chunk & 15) << 2;
                float4 v = *reinterpret_cast<const float4*>(
                    A + ((size_t)t * HH + ks + k) * BB + b0 + b4);
                *reinterpret_cast<float4*>(&At[k * 68 + b4]) = v;
            }
        }
#pragma unroll
        for (int q = 0; q < 4; q++) {
            int chunk = tid + 256 * q;              // 1024 float4 chunks
            int col   = chunk >> 3;
            int kq    = (chunk & 7) << 2;
            float4 v  = *reinterpret_cast<const float4*>(
                W + (size_t)(n0 + col) * K + ks + kq);
            Wt[(kq + 0) * 130 + col] = v.x;
            Wt[(kq + 1) * 130 + col] = v.y;
            Wt[(kq + 2) * 130 + col] = v.z;
            Wt[(kq + 3) * 130 + col] = v.w;
        }
        __syncthreads();

#pragma unroll 8
        for (int k = 0; k < 32; k++) {
            ull w[4];
#pragma unroll
            for (int j = 0; j < 4; j++)
                w[j] = *reinterpret_cast<const ull*>(
                    &Wt[k * 130 + 2 * tx + 32 * j]);
#pragma unroll
            for (int r = 0; r < 4; r++) {
                float a = At[k * 68 + ty + 16 * r];
                ull aa = pack2(a, a);
#pragma unroll
                for (int j = 0; j < 4; j++) fma2(acc[r][j], aa, w[j]);
            }
        }
        __syncthreads();
    }

#pragma unroll
    for (int r = 0; r < 4; r++) {
        int m = m0 + ty + 16 * r;
#pragma unroll
        for (int j = 0; j < 4; j++) {
            int gc = n0 + 2 * tx + 32 * j;
            float lo, hi;
            unpack2(acc[r][j], lo, hi);
            float2 o;
            o.x = lo + bih[gc]     + bhh[gc];
            o.y = hi + bih[gc + 1] + bhh[gc + 1];
            *reinterpret_cast<float2*>(&out[(size_t)m * G4H + gc]) = o;
        }
    }
}

// ================================================================================
// Persistent recurrent kernel: one layer, all 512 steps.
// 16 CTA-octets; each octet serves TWO independent 8-batch groups (A, B),
// interleaved per step so group A's h-handoff round trip (fence, red, peer L2
// poll, re-stage) is hidden under group B's compute phase and vice versa.
// Both groups share the SMEM-resident W_hh slice (32 hcols x 4 gates x 256 k).
// 8 warps = 2 gatecol-halves x 4 K-quarters; per-warp inner loop: 8 FFMA2 +
// 5 LDS + 2 MOV per k (FMA-bound). Partial sums combined through Gs SMEM.
// ================================================================================
template<bool STORE_SEQ>
__global__ __launch_bounds__(RTHREADS, 1)
void lstm_persist(const float* __restrict__ Whh, int layer)
{
    extern __shared__ float sm[];
    float* Wt = sm;                      // [256][130]  k-major, gidx = g*32 + c
    float* Xs = Wt + 256 * 130;          // [256][12]   k-major h tile [k][b], b<8
    float* Gs = Xs + 256 * 12;           // [4 kq][128 gidx][10]  quarter-sums

    const int tid  = threadIdx.x;
    const int wid  = tid >> 5;
    const int ch   = wid & 1;            // gatecol half: gidx 64*ch .. 64*ch+63
    const int kq   = wid >> 1;           // K-quarter 0..3 (64 k each)
    const int lane = tid & 31;
    const int cb   = blockIdx.x & 7;     // hcol slice 0..7
    const int bi   = blockIdx.x >> 3;    // batch octet 0..15
    const int jb   = cb * 32;
    const int bb   = bi * 16;

    unsigned* ctrs[2] = { &g_ctr[layer][(bi * 2 + 0) * 64],
                          &g_ctr[layer][(bi * 2 + 1) * 64] };
    unsigned target[2] = { GRPSZ, GRPSZ };

    // ---- one-time: load W_hh slice transposed into SMEM (128 gidx x 256 k) ----
#pragma unroll 4
    for (int it = 0; it < 32; it++) {
        int idx = it * RTHREADS + tid;       // 8192 float4 chunks
        int r   = idx >> 6;                  // gidx 0..127 (g*32 + c)
        int k4  = (idx & 63) << 2;
        int gcol = (r >> 5) * HH + jb + (r & 31);
        float4 v = *reinterpret_cast<const float4*>(Whh + (size_t)gcol * HH + k4);
        Wt[(k4 + 0) * 130 + r] = v.x;
        Wt[(k4 + 1) * 130 + r] = v.y;
        Wt[(k4 + 2) * 130 + r] = v.z;
        Wt[(k4 + 3) * 130 + r] = v.w;
    }
    // ---- zero this CTA's slice of h(-1): hcols jb..jb+31, batch bb..bb+15 ----
    {
        int r   = tid >> 3;                  // 0..31 (hcol within slice)
        int c2i = (tid & 7) << 1;            // 0,2,...,14
        float2 z = make_float2(0.f, 0.f);
        __stcg(reinterpret_cast<float2*>(
            &g_hT[0][(size_t)(jb + r) * BB + bb + c2i]), z);
    }
    __syncthreads();
    if (tid == 0) {
        __threadfence();
        bar_red(ctrs[0]);
        bar_red(ctrs[1]);
    }

    // epilogue item owned by this thread: hcol j (0..31), batch row bq (0..7)
    const int j  = tid & 31;
    const int bq = tid >> 5;
    float creg[2] = {0.f, 0.f};
    float xq[2][4];
    // prefetch xproj tiles for t=0, both groups
#pragma unroll
    for (int ab = 0; ab < 2; ab++) {
        const float* xb = g_xproj + ((size_t)0 * BB + bb + 8 * ab + bq) * G4H
                        + jb + j;
#pragma unroll
        for (int g = 0; g < 4; g++)
            xq[ab][g] = __ldcg(xb + g * HH);
    }

    for (int t = 0; t < TT; t++) {
        const float* __restrict__ hprev = g_hT[t & 1];
        float* __restrict__ hnext = g_hT[(t & 1) ^ 1];

#pragma unroll
        for (int ab = 0; ab < 2; ab++) {
            const int bbx = bb + 8 * ab;

            // ---- wait: this group's 8 CTAs published h(t-1) ----
            // (published one full phase ago -> poll succeeds near-immediately)
            if (tid == 0) {
                while (ld_acq(ctrs[ab]) < target[ab]) {}
            }
            __syncthreads();
            target[ab] += GRPSZ;

            // ---- stage h tile [256 k][8 b] into Xs (512 float4, L2 reads) ----
#pragma unroll
            for (int q = 0; q < 2; q++) {
                int chunk = q * RTHREADS + tid;  // 0..511
                int k  = chunk >> 1;
                int c4 = (chunk & 1) << 2;
                float4 v = __ldcg(reinterpret_cast<const float4*>(
                    hprev + (size_t)k * BB + bbx + c4));
                *reinterpret_cast<float4*>(&Xs[k * 12 + c4]) = v;
            }
            __syncthreads();

            // ---- inner GEMM: gidx 64ch+2lane(+1), K-quarter kq, 8 rows ----
            ull acc[4][2];
#pragma unroll
            for (int p = 0; p < 4; p++) { acc[p][0] = 0ull; acc[p][1] = 0ull; }
            {
                const float* xk = &Xs[(kq * 64) * 12];
                const float* wk = &Wt[(kq * 64) * 130 + ch * 64 + 2 * lane];
#pragma unroll 8
                for (int k = 0; k < 64; k++) {
                    const float* xr = xk + k * 12;
                    ull A0 = *reinterpret_cast<const ull*>(xr + 0);
                    ull A1 = *reinterpret_cast<const ull*>(xr + 2);
                    ull A2 = *reinterpret_cast<const ull*>(xr + 4);
                    ull A3 = *reinterpret_cast<const ull*>(xr + 6);
                    float2 wv = *reinterpret_cast<const float2*>(wk + k * 130);
                    ull W0 = pack2(wv.x, wv.x);
                    ull W1 = pack2(wv.y, wv.y);
                    fma2(acc[0][0], A0, W0); fma2(acc[0][1], A0, W1);
                    fma2(acc[1][0], A1, W0); fma2(acc[1][1], A1, W1);
                    fma2(acc[2][0], A2, W0); fma2(acc[2][1], A2, W1);
                    fma2(acc[3][0], A3, W0); fma2(acc[3][1], A3, W1);
                }
            }

            // ---- quarter-sum exchange: Gs[kq][gidx][b] ----
            {
                float* gsh = Gs + kq * (128 * 10);
                int col0 = ch * 64 + 2 * lane;
#pragma unroll
                for (int p = 0; p < 4; p++) {
                    *reinterpret_cast<ull*>(&gsh[(col0    ) * 10 + 2 * p]) = acc[p][0];
                    *reinterpret_cast<ull*>(&gsh[(col0 + 1) * 10 + 2 * p]) = acc[p][1];
                }
            }
            __syncthreads();

            // ---- epilogue: thread owns (hcol j, batch row bq) ----
            float gsv[4];
#pragma unroll
            for (int g = 0; g < 4; g++) {
                float s = xq[ab][g];
#pragma unroll
                for (int q2 = 0; q2 < 4; q2++)
                    s += Gs[(q2 * 128 + g * 32 + j) * 10 + bq];
                gsv[g] = s;
            }

            // prefetch next step's xproj tile (overlaps MUFU chain + publish)
            if (t + 1 < TT) {
                const float* xb = g_xproj + ((size_t)(t + 1) * BB + bbx + bq) * G4H
                                + jb + j;
#pragma unroll
                for (int g = 0; g < 4; g++)
                    xq[ab][g] = __ldcg(xb + g * HH);
            }

            float iv = sigf(gsv[0]);
            float fv = sigf(gsv[1]);
            float gv = tanf_fast(gsv[2]);
            float ov = sigf(gsv[3]);
            float c  = fv * creg[ab] + iv * gv;
            creg[ab] = c;
            float hv = ov * tanf_fast(c);

            size_t hoff = (size_t)(jb + j) * BB + bbx + bq;
            __stcg(hnext + hoff, hv);
            if (STORE_SEQ)
                __stcg(g_h0T + (size_t)t * (HH * BB) + hoff, hv);

            // ---- publish h(t) for this group (publisher != poller warp) ----
            __syncthreads();   // all h stores issued; Xs/Gs free for next phase
            if (t + 1 < TT && tid == 32 + 32 * ab) {
                __threadfence();
                bar_red(ctrs[ab]);
            }
        }
    }
}

// zero barrier counters (run once per replay, before everything)
__global__ void init_kernel()
{
    int i = threadIdx.x;
    for (; i < 2 * 32 * 64; i += blockDim.x)
        (&g_ctr[0][0])[i] = 0u;
}

// out[b] = h_last[b] . fc_w + fc_b. TT even -> final h of layer 1 is g_hT[0] ([H][B]).
__global__ void fc_kernel(const float* __restrict__ w,
                          const float* __restrict__ bias,
                          float* __restrict__ out)
{
    int b = threadIdx.x;   // 256 threads, 1 block
    float s = 0.f;
#pragma unroll 8
    for (int j = 0; j < HH; j++)
        s += g_hT[0][(size_t)j * BB + b] * w[j];
    out[b] = s + bias[0];
}

extern "C" void kernel_launch(void* const* d_in, const int* in_sizes, int n_in,
                              void* d_out, int out_size)
{
    const float* x     = (const float*)d_in[0];
    const float* W_ih0 = (const float*)d_in[1];
    const float* W_hh0 = (const float*)d_in[2];
    const float* b_ih0 = (const float*)d_in[3];
    const float* b_hh0 = (const float*)d_in[4];
    const float* W_ih1 = (const float*)d_in[5];
    const float* W_hh1 = (const float*)d_in[6];
    const float* b_ih1 = (const float*)d_in[7];
    const float* b_hh1 = (const float*)d_in[8];
    const float* fc_w  = (const float*)d_in[9];
    const float* fc_b  = (const float*)d_in[10];
    float* out = (float*)d_out;
    (void)in_sizes; (void)n_in; (void)out_size;

    // Wt + Xs + Gs
    const int rsmem = (256 * 130 + 256 * 12 + 4 * 128 * 10) * sizeof(float); // 165,888 B
    static bool attr_done = false;
    if (!attr_done) {
        cudaFuncSetAttribute(lstm_persist<true>,
                             cudaFuncAttributeMaxDynamicSharedMemorySize, rsmem);
        cudaFuncSetAttribute(lstm_persist<false>,
                             cudaFuncAttributeMaxDynamicSharedMemorySize, rsmem);
        attr_done = true;
    }

    float* xproj_ptr = nullptr;
    cudaGetSymbolAddress((void**)&xproj_ptr, g_xproj);
    float* h0T_ptr = nullptr;
    cudaGetSymbolAddress((void**)&h0T_ptr, g_h0T);

    init_kernel<<<1, 256>>>();

    dim3 ggrid(TT * BB / 64, G4H / 128);  // (2048, 8)

    // layer 0: input projection (time-parallel), then recurrence
    xproj_gemm<DD, 0><<<ggrid, 256>>>(x, W_ih0, b_ih0, b_hh0, xproj_ptr);
    lstm_persist<true><<<NBLK, RTHREADS, rsmem>>>(W_hh0, 0);

    // layer 1: input projection from transposed layer-0 sequence, then recurrence
    xproj_gemm<HH, 1><<<ggrid, 256>>>(h0T_ptr, W_ih1, b_ih1, b_hh1, xproj_ptr);
    lstm_persist<false><<<NBLK, RTHREADS, rsmem>>>(W_hh1, 1);

    fc_kernel<<<1, BB>>>(fc_w, fc_b, out);
}

// round 17
// speedup vs baseline: 1.7402x; 1.7402x over previous
#include <cuda_runtime.h>
#include <cuda_bf16.h>
#include <math.h>
#include <stdint.h>

// Problem constants
#define BB 256   // batch
#define TT 512   // time steps
#define DD 64    // input dim (layer 0)
#define HH 256   // hidden dim
#define G4H 1024 // 4*H

#define NBLK 128     // persistent grid (16 groups x 8 CTAs), 1 block/SM
#define RTHREADS 256 // 8 warps = 4 gidx-quarters x 2 K-halves
#define GRPSZ 8      // CTAs per sync group (one 16-batch slice)
#define KP 264       // bf16 row stride (conflict-free: 132 words ≡ 4 mod 32)

typedef unsigned long long ull;

// ---------------- scratch (__device__ globals; no allocations allowed) ----------
__device__ float    g_xproj[(size_t)TT * BB * G4H]; // 512 MB: x @ W_ih^T + bias, [T][B][4H]
__device__ float    g_h0seq[(size_t)TT * BB * HH];  // 128 MB: layer-0 outputs [T][B][H]
__device__ float    g_hB[2][BB * HH];               // ping-pong h state, [B][H]
__device__ unsigned g_ctr[2][16 * 64];              // per-group counters, 256B apart

// ---------------- packed fp32x2 helpers (xproj GEMM) -----------------------------
__device__ __forceinline__ ull pack2(float lo, float hi) {
    ull r;
    asm("mov.b64 %0, {%1, %2};" : "=l"(r) : "f"(lo), "f"(hi));
    return r;
}
__device__ __forceinline__ void unpack2(ull v, float& lo, float& hi) {
    asm("mov.b64 {%0, %1}, %2;" : "=f"(lo), "=f"(hi) : "l"(v));
}
__device__ __forceinline__ void fma2(ull& d, ull a, ull b) {
    asm("fma.rn.f32x2 %0, %1, %2, %0;" : "+l"(d) : "l"(a), "l"(b));
}

// ---------------- fast activations (MUFU-based, ~1e-6 rel err) ------------------
__device__ __forceinline__ float sigf(float x) {
    return __fdividef(1.0f, 1.0f + __expf(-x));
}
__device__ __forceinline__ float tanf_fast(float x) {
    return __fdividef(2.0f, 1.0f + __expf(-2.0f * x)) - 1.0f;
}

// ---------------- group barrier primitives ---------------------------------------
__device__ __forceinline__ void bar_red(unsigned* ctr) {
    asm volatile("red.release.gpu.add.u32 [%0], 1;" :: "l"(ctr) : "memory");
}
__device__ __forceinline__ unsigned ld_acq(const unsigned* p) {
    unsigned v;
    asm volatile("ld.acquire.gpu.u32 %0, [%1];" : "=r"(v) : "l"(p) : "memory");
    return v;
}

// ---------------- HMMA: mma.sync m16n8k16 bf16 (baseline PTX, no 'a' target) ----
__device__ __forceinline__ void mma16816(float* d, const uint32_t* a, const uint32_t* b) {
    asm volatile(
        "mma.sync.aligned.m16n8k16.row.col.f32.bf16.bf16.f32 "
        "{%0,%1,%2,%3}, {%4,%5,%6,%7}, {%8,%9}, {%0,%1,%2,%3};"
        : "+f"(d[0]), "+f"(d[1]), "+f"(d[2]), "+f"(d[3])
        : "r"(a[0]), "r"(a[1]), "r"(a[2]), "r"(a[3]), "r"(b[0]), "r"(b[1]));
}

// split x,y into bf16 hi pair + bf16 lo (residual) pair
__device__ __forceinline__ void split2(float x, float y, uint32_t& hi, uint32_t& lo) {
    __nv_bfloat162 h2 = __floats2bfloat162_rn(x, y);
    float rx = x - __bfloat162float(h2.x);
    float ry = y - __bfloat162float(h2.y);
    __nv_bfloat162 l2 = __floats2bfloat162_rn(rx, ry);
    hi = *reinterpret_cast<uint32_t*>(&h2);
    lo = *reinterpret_cast<uint32_t*>(&l2);
}

// SMEM byte offsets; all bases 16B-aligned
#define SM_WHI  0                      // W_hi: 128 x KP bf16 (67,584 B)
#define SM_WLO  67584                  // W_lo
#define SM_BHI  135168                 // h_hi: 16 x KP bf16 (8,448 B)
#define SM_BLO  143616                 // h_lo
#define SM_GS   152064                 // Gs: [2 kh][128 gidx][20] fp32 (20,480 B)
#define SM_TOT  172544

// ================================================================================
// Input-projection GEMM (best-measured version):
// out[m][gc] = sum_k A[m][k] * W[gc][k] + b_ih[gc] + b_hh[gc], m = t*BB + b.
// AMODE 0: A = x [B][T][D].  AMODE 2: A plain row-major [m][K] (g_h0seq).
// ================================================================================
template<int K, int AMODE>
__global__ __launch_bounds__(256)
void xproj_gemm(const float* __restrict__ A,
                const float* __restrict__ W,
                const float* __restrict__ bih,
                const float* __restrict__ bhh,
                float* __restrict__ out)
{
    __shared__ float At[32 * 68];    // [k][row], padded
    __shared__ float Wt[32 * 130];   // [k][col], even pad (8B-aligned rows)

    const int tid = threadIdx.x;
    const int tx  = tid & 15;        // col-pair lane: cols 2tx + 32j
    const int ty  = tid >> 4;        // rows ty + 16r
    const int m0  = blockIdx.x * 64;
    const int n0  = blockIdx.y * 128;

    ull acc[4][4];
#pragma unroll
    for (int r = 0; r < 4; r++)
#pragma unroll
        for (int j = 0; j < 4; j++) acc[r][j] = 0ull;

    for (int ks = 0; ks < K; ks += 32) {
#pragma unroll
        for (int q = 0; q < 2; q++) {
            int chunk = tid + 256 * q;          // 512 float4 chunks
            int row   = chunk >> 3;
            int kq    = (chunk & 7) << 2;
            int m     = m0 + row;
            const float* ap;
            if (AMODE == 0)
                ap = A + (size_t)(m & 255) * (TT * DD) + (size_t)(m >> 8) * DD + ks + kq;
            else
                ap = A + (size_t)m * K + ks + kq;
            float4 v = *reinterpret_cast<const float4*>(ap);
            At[(kq + 0) * 68 + row] = v.x;
            At[(kq + 1) * 68 + row] = v.y;
            At[(kq + 2) * 68 + row] = v.z;
            At[(kq + 3) * 68 + row] = v.w;
        }
#pragma unroll
        for (int q = 0; q < 4; q++) {
            int chunk = tid + 256 * q;              // 1024 float4 chunks
            int col   = chunk >> 3;
            int kq    = (chunk & 7) << 2;
            float4 v  = *reinterpret_cast<const float4*>(
                W + (size_t)(n0 + col) * K + ks + kq);
            Wt[(kq + 0) * 130 + col] = v.x;
            Wt[(kq + 1) * 130 + col] = v.y;
            Wt[(kq + 2) * 130 + col] = v.z;
            Wt[(kq + 3) * 130 + col] = v.w;
        }
        __syncthreads();

#pragma unroll 8
        for (int k = 0; k < 32; k++) {
            ull w[4];
#pragma unroll
            for (int j = 0; j < 4; j++)
                w[j] = *reinterpret_cast<const ull*>(&Wt[k * 130 + 2 * tx + 32 * j]);
#pragma unroll
            for (int r = 0; r < 4; r++) {
                float a = At[k * 68 + ty + 16 * r];
                ull aa = pack2(a, a);
#pragma unroll
                for (int j = 0; j < 4; j++) fma2(acc[r][j], aa, w[j]);
            }
        }
        __syncthreads();
    }

#pragma unroll
    for (int r = 0; r < 4; r++) {
        int m = m0 + ty + 16 * r;
#pragma unroll
        for (int j = 0; j < 4; j++) {
            int gc = n0 + 2 * tx + 32 * j;
            float lo, hi;
            unpack2(acc[r][j], lo, hi);
            float2 o;
            o.x = lo + bih[gc]     + bhh[gc];
            o.y = hi + bih[gc + 1] + bhh[gc + 1];
            *reinterpret_cast<float2*>(&out[(size_t)m * G4H + gc]) = o;
        }
    }
}

// ================================================================================
// Persistent recurrent kernel: HMMA (mma.sync bf16, 3-term split) GEMM.
// 16 groups (16-batch slices) x 8 CTAs (32-hcol slices = 128 gidx rows each).
// 8 warps = 4 gidx-quarters x 2 K-halves; each warp: D[32,16] over 128 k via
// 2x2 m16n8k16 tiles, fragments loaded with plain LDS at documented coords
// (W[gidx][k], h[b][k], both k-contiguous bf16, stride KP=264 conflict-free).
// Partial sums merged through Gs SMEM; epilogue/sync = R14 8162us winner.
// ================================================================================
template<bool STORE_SEQ>
__global__ __launch_bounds__(RTHREADS, 1)
void lstm_persist(const float* __restrict__ Whh, int layer)
{
    extern __shared__ char smc[];
    uint16_t* whi = reinterpret_cast<uint16_t*>(smc + SM_WHI);
    uint16_t* wlo = reinterpret_cast<uint16_t*>(smc + SM_WLO);
    uint16_t* bhi = reinterpret_cast<uint16_t*>(smc + SM_BHI);
    uint16_t* blo = reinterpret_cast<uint16_t*>(smc + SM_BLO);
    float*    Gs  = reinterpret_cast<float*>(smc + SM_GS);

    const int tid  = threadIdx.x;
    const int wid  = tid >> 5;
    const int wq   = wid & 3;            // gidx quarter: rows 32wq..32wq+31
    const int kh   = wid >> 2;           // K-half 0..1 (128 k each)
    const int lane = tid & 31;
    const int la4  = lane >> 2;          // 0..7
    const int lk   = (lane & 3) * 2;     // 0,2,4,6
    const int cb   = blockIdx.x & 7;     // hcol slice 0..7
    const int bi   = blockIdx.x >> 3;    // batch group 0..15
    const int jb   = cb * 32;
    const int bb   = bi * 16;

    unsigned* ctr = &g_ctr[layer][bi * 64];
    unsigned  target = GRPSZ;

    // ---- one-time: split W_hh slice (128 gidx x 256 k) into bf16 hi/lo SMEM ----
#pragma unroll 4
    for (int it = 0; it < 16; it++) {
        int idx = it * RTHREADS + tid;       // 4096 chunks of 8 k
        int r   = idx >> 5;                  // gidx 0..127 (g*32 + c)
        int k0  = (idx & 31) << 3;           // 0..248
        int gcol = (r >> 5) * HH + jb + (r & 31);
        const float* wp = Whh + (size_t)gcol * HH + k0;
        float4 v0 = *reinterpret_cast<const float4*>(wp);
        float4 v1 = *reinterpret_cast<const float4*>(wp + 4);
        uint4 Hh, Ll;
        split2(v0.x, v0.y, Hh.x, Ll.x);
        split2(v0.z, v0.w, Hh.y, Ll.y);
        split2(v1.x, v1.y, Hh.z, Ll.z);
        split2(v1.z, v1.w, Hh.w, Ll.w);
        *reinterpret_cast<uint4*>(whi + r * KP + k0) = Hh;
        *reinterpret_cast<uint4*>(wlo + r * KP + k0) = Ll;
    }
    // ---- zero this CTA's slice of h(-1): batch bb..bb+15, hcols jb..jb+31 ----
    {
        int idx2 = tid * 2;
        int b = idx2 >> 5, c = idx2 & 31;
        float2 z = make_float2(0.f, 0.f);
        __stcg(reinterpret_cast<float2*>(&g_hB[0][(size_t)(bb + b) * HH + jb + c]), z);
    }
    __syncthreads();
    if (tid == 0) { __threadfence(); bar_red(ctr); }

    // epilogue item: hcol j (0..31), batch pair bh (0..7) -> batches 2bh, 2bh+1
    const int j  = tid & 31;
    const int bh = tid >> 5;
    float creg[2] = {0.f, 0.f};

    // prefetch xproj tile for t=0
    float xq[4][2];
    {
        const float* xb = g_xproj + ((size_t)0 * BB + bb + 2 * bh) * G4H + jb + j;
#pragma unroll
        for (int g = 0; g < 4; g++) {
            xq[g][0] = __ldcg(xb + g * HH);
            xq[g][1] = __ldcg(xb + G4H + g * HH);
        }
    }

    for (int t = 0; t < TT; t++) {
        // ---- wait: our 8-CTA group published h(t-1) ----
        if (tid == 0) {
            while (ld_acq(ctr) < target) {}
        }
        __syncthreads();
        target += GRPSZ;

        const float* __restrict__ hprev = g_hB[t & 1];
        float* __restrict__ hnext = g_hB[(t & 1) ^ 1];

        // ---- stage h (16 b x 256 k) -> bf16 hi/lo SMEM [b][k] ----
#pragma unroll
        for (int q = 0; q < 2; q++) {
            int chunk = q * RTHREADS + tid;      // 512 chunks of 8 k
            int b  = chunk >> 5;
            int k0 = (chunk & 31) << 3;
            const float* hp = hprev + (size_t)(bb + b) * HH + k0;
            float4 v0 = __ldcg(reinterpret_cast<const float4*>(hp));
            float4 v1 = __ldcg(reinterpret_cast<const float4*>(hp + 4));
            uint4 Hh, Ll;
            split2(v0.x, v0.y, Hh.x, Ll.x);
            split2(v0.z, v0.w, Hh.y, Ll.y);
            split2(v1.x, v1.y, Hh.z, Ll.z);
            split2(v1.z, v1.w, Hh.w, Ll.w);
            *reinterpret_cast<uint4*>(bhi + b * KP + k0) = Hh;
            *reinterpret_cast<uint4*>(blo + b * KP + k0) = Ll;
        }
        __syncthreads();

        // ---- HMMA GEMM: warp (wq, kh): D[32 gidx, 16 b] over 128 k ----
        float d[2][2][4];
#pragma unroll
        for (int mt = 0; mt < 2; mt++)
#pragma unroll
            for (int nt = 0; nt < 2; nt++)
#pragma unroll
                for (int e = 0; e < 4; e++) d[mt][nt][e] = 0.f;

#pragma unroll
        for (int kc = 0; kc < 8; kc++) {
            int k0 = kh * 128 + kc * 16;
            uint32_t aH[2][4], aL[2][4], bH[2][2], bL[2][2];
#pragma unroll
            for (int mt = 0; mt < 2; mt++) {
                int r0 = (wq * 32 + mt * 16 + la4) * KP + k0 + lk;
                aH[mt][0] = *reinterpret_cast<const uint32_t*>(whi + r0);
                aH[mt][1] = *reinterpret_cast<const uint32_t*>(whi + r0 + 8 * KP);
                aH[mt][2] = *reinterpret_cast<const uint32_t*>(whi + r0 + 8);
                aH[mt][3] = *reinterpret_cast<const uint32_t*>(whi + r0 + 8 * KP + 8);
                aL[mt][0] = *reinterpret_cast<const uint32_t*>(wlo + r0);
                aL[mt][1] = *reinterpret_cast<const uint32_t*>(wlo + r0 + 8 * KP);
                aL[mt][2] = *reinterpret_cast<const uint32_t*>(wlo + r0 + 8);
                aL[mt][3] = *reinterpret_cast<const uint32_t*>(wlo + r0 + 8 * KP + 8);
            }
#pragma unroll
            for (int nt = 0; nt < 2; nt++) {
                int rb = (nt * 8 + la4) * KP + k0 + lk;
                bH[nt][0] = *reinterpret_cast<const uint32_t*>(bhi + rb);
                bH[nt][1] = *reinterpret_cast<const uint32_t*>(bhi + rb + 8);
                bL[nt][0] = *reinterpret_cast<const uint32_t*>(blo + rb);
                bL[nt][1] = *reinterpret_cast<const uint32_t*>(blo + rb + 8);
            }
#pragma unroll
            for (int mt = 0; mt < 2; mt++)
#pragma unroll
                for (int nt = 0; nt < 2; nt++) {
                    mma16816(d[mt][nt], aH[mt], bH[nt]);  // hi*hi
                    mma16816(d[mt][nt], aH[mt], bL[nt]);  // hi*lo
                    mma16816(d[mt][nt], aL[mt], bH[nt]);  // lo*hi
                }
        }

        // ---- partial-sum exchange: Gs[kh][gidx][batch] ----
        {
            float* gsh = Gs + kh * (128 * 20);
#pragma unroll
            for (int mt = 0; mt < 2; mt++)
#pragma unroll
                for (int nt = 0; nt < 2; nt++) {
                    int gi = wq * 32 + mt * 16 + la4;
                    int bc = nt * 8 + lk;
                    *reinterpret_cast<float2*>(&gsh[gi * 20 + bc]) =
                        make_float2(d[mt][nt][0], d[mt][nt][1]);
                    *reinterpret_cast<float2*>(&gsh[(gi + 8) * 20 + bc]) =
                        make_float2(d[mt][nt][2], d[mt][nt][3]);
                }
        }
        __syncthreads();

        // ---- epilogue: thread owns (hcol j, batch pair bh); sum the K-halves ----
        float gs[4][2];
#pragma unroll
        for (int g = 0; g < 4; g++) {
            float2 v0 = *reinterpret_cast<const float2*>(&Gs[(g * 32 + j) * 20 + 2 * bh]);
            float2 v1 = *reinterpret_cast<const float2*>(
                &Gs[128 * 20 + (g * 32 + j) * 20 + 2 * bh]);
            gs[g][0] = v0.x + v1.x + xq[g][0];
            gs[g][1] = v0.y + v1.y + xq[g][1];
        }

        // prefetch next step's xproj tile (overlaps MUFU chain + publish)
        if (t + 1 < TT) {
            const float* xb = g_xproj + ((size_t)(t + 1) * BB + bb + 2 * bh) * G4H
                            + jb + j;
#pragma unroll
            for (int g = 0; g < 4; g++) {
                xq[g][0] = __ldcg(xb + g * HH);
                xq[g][1] = __ldcg(xb + G4H + g * HH);
            }
        }

#pragma unroll
        for (int b = 0; b < 2; b++) {
            float iv = sigf(gs[0][b]);
            float fv = sigf(gs[1][b]);
            float gv = tanf_fast(gs[2][b]);
            float ov = sigf(gs[3][b]);
            float c  = fv * creg[b] + iv * gv;
            creg[b]  = c;
            float hv = ov * tanf_fast(c);
            size_t hoff = (size_t)(bb + 2 * bh + b) * HH + jb + j;
            __stcg(hnext + hoff, hv);
            if (STORE_SEQ)
                __stcg(g_h0seq + (size_t)t * (BB * HH) + hoff, hv);
        }

        // ---- arrive: publish h(t) to the group ----
        __syncthreads();   // all h stores issued; Gs/h-stage buffers free next step
        if (tid == 0) { __threadfence(); bar_red(ctr); }
    }
}

// zero barrier counters (run once per replay, before everything)
__global__ void init_kernel()
{
    int i = threadIdx.x;
    for (; i < 2 * 16 * 64; i += blockDim.x)
        (&g_ctr[0][0])[i] = 0u;
}

// out[b] = h_last[b] . fc_w + fc_b. TT even -> final h of layer 1 is g_hB[0] ([B][H]).
__global__ void fc_kernel(const float* __restrict__ w,
                          const float* __restrict__ bias,
                          float* __restrict__ out)
{
    int b    = blockIdx.x * 8 + (threadIdx.x >> 5);
    int lane = threadIdx.x & 31;
    const float* h = &g_hB[0][(size_t)b * HH];
    float s = 0.f;
#pragma unroll
    for (int q = 0; q < HH / 32; q++)
        s += h[lane + 32 * q] * w[lane + 32 * q];
#pragma unroll
    for (int o = 16; o; o >>= 1) s += __shfl_xor_sync(0xffffffffu, s, o);
    if (lane == 0) out[b] = s + bias[0];
}

extern "C" void kernel_launch(void* const* d_in, const int* in_sizes, int n_in,
                              void* d_out, int out_size)
{
    const float* x     = (const float*)d_in[0];
    const float* W_ih0 = (const float*)d_in[1];
    const float* W_hh0 = (const float*)d_in[2];
    const float* b_ih0 = (const float*)d_in[3];
    const float* b_hh0 = (const float*)d_in[4];
    const float* W_ih1 = (const float*)d_in[5];
    const float* W_hh1 = (const float*)d_in[6];
    const float* b_ih1 = (const float*)d_in[7];
    const float* b_hh1 = (const float*)d_in[8];
    const float* fc_w  = (const float*)d_in[9];
    const float* fc_b  = (const float*)d_in[10];
    float* out = (float*)d_out;
    (void)in_sizes; (void)n_in; (void)out_size;

    static bool attr_done = false;
    if (!attr_done) {
        cudaFuncSetAttribute(lstm_persist<true>,
                             cudaFuncAttributeMaxDynamicSharedMemorySize, SM_TOT);
        cudaFuncSetAttribute(lstm_persist<false>,
                             cudaFuncAttributeMaxDynamicSharedMemorySize, SM_TOT);
        attr_done = true;
    }

    float* xproj_ptr = nullptr;
    cudaGetSymbolAddress((void**)&xproj_ptr, g_xproj);
    float* h0seq_ptr = nullptr;
    cudaGetSymbolAddress((void**)&h0seq_ptr, g_h0seq);

    init_kernel<<<1, 256>>>();

    dim3 ggrid(TT * BB / 64, G4H / 128);  // (2048, 8)

    // layer 0: input projection (time-parallel), then HMMA recurrence
    xproj_gemm<DD, 0><<<ggrid, 256>>>(x, W_ih0, b_ih0, b_hh0, xproj_ptr);
    lstm_persist<true><<<NBLK, RTHREADS, SM_TOT>>>(W_hh0, 0);

    // layer 1: input projection from layer-0 sequence, then recurrence
    xproj_gemm<HH, 2><<<ggrid, 256>>>(h0seq_ptr, W_ih1, b_ih1, b_hh1, xproj_ptr);
    lstm_persist<false><<<NBLK, RTHREADS, SM_TOT>>>(W_hh1, 1);

    fc_kernel<<<BB / 8, 256>>>(fc_w, fc_b, out);
}